// round 11
// baseline (speedup 1.0000x reference)
#include <cuda_runtime.h>
#include <math.h>
#include <stdint.h>

// Problem constants
#define B_  4
#define C_  128
#define H_B 512
#define W_B 512
#define H_C 64
#define W_C 2048
#define BC_ (B_ * C_)          // 512 planes

#define WCH 512                // w columns per CTA
#define NCHUNK (W_C / WCH)     // 4 chunks per plane -> 2048 CTAs
#define CHUNK_BYTES (WCH * 4)  // 2048 bytes

__device__ __forceinline__ uint32_t smem_u32(const void* p) {
    uint32_t a;
    asm("{ .reg .u64 t; cvta.to.shared.u64 t, %1; cvt.u32.u64 %0, t; }"
        : "=r"(a) : "l"(p));
    return a;
}

// One CTA per (bc, 512-wide w chunk).  256 threads.
// Phase A: gather 2 column values per thread (sincosf + 4 LDG each) -> SMEM.
// Phase B: 8 warps x 8 TMA bulk-copies of the same 2KB SMEM chunk to the 64
// output rows.  No per-thread store stream: the async engines keep the
// L2/DRAM write queues full with zero SM scheduling in the loop.
__global__ __launch_bounds__(256) void bev2cyl_tma(const float* __restrict__ bev,
                                                   float* __restrict__ out) {
    __shared__ __align__(128) float s_col[WCH];

    const int t     = threadIdx.x;
    const int bc    = blockIdx.x >> 2;            // / NCHUNK
    const int chunk = blockIdx.x & (NCHUNK - 1);
    const int wbase = chunk * WCH;

    const float* __restrict__ plane = bev + (size_t)bc * (H_B * W_B);

    // ---- Phase A: two columns per thread ----
    const float STEP = (float)(6.283185307179586 / 2047.0);
#pragma unroll
    for (int k = 0; k < 2; k++) {
        int wi = k * 256 + t;                     // 0..511 within chunk
        int w  = wbase + wi;

        float phi = fmaf((float)w, STEP, -3.14159265358979f);
        float s, c;
        sincosf(phi, &s, &c);
        float x = (50.0f * c + 50.0f) * (511.0f / 100.0f);
        float y = (50.0f - 50.0f * s) * (511.0f / 100.0f);

        float fx0 = floorf(x), fy0 = floorf(y);
        int x0 = (int)fx0, y0 = (int)fy0;
        int x1 = x0 + 1,  y1 = y0 + 1;
        float wx1 = x - fx0, wx0 = 1.0f - wx1;
        float wy1 = y - fy0, wy0 = 1.0f - wy1;

        bool vx0 = (x0 >= 0) && (x0 < W_B);
        bool vx1 = (x1 >= 0) && (x1 < W_B);
        bool vy0 = (y0 >= 0) && (y0 < H_B);
        bool vy1 = (y1 >= 0) && (y1 < H_B);

        int x0c = min(max(x0, 0), W_B - 1);
        int x1c = min(max(x1, 0), W_B - 1);
        int y0c = min(max(y0, 0), H_B - 1);
        int y1c = min(max(y1, 0), H_B - 1);

        float w00 = (vx0 && vy0) ? wx0 * wy0 : 0.0f;
        float w10 = (vx1 && vy0) ? wx1 * wy0 : 0.0f;
        float w01 = (vx0 && vy1) ? wx0 * wy1 : 0.0f;
        float w11 = (vx1 && vy1) ? wx1 * wy1 : 0.0f;

        float p00 = __ldg(plane + y0c * W_B + x0c);
        float p10 = __ldg(plane + y0c * W_B + x1c);
        float p01 = __ldg(plane + y1c * W_B + x0c);
        float p11 = __ldg(plane + y1c * W_B + x1c);

        s_col[wi] = p00 * w00 + p10 * w10 + p01 * w01 + p11 * w11;
    }
    __syncthreads();

    // ---- Phase B: TMA bulk stores, 8 rows per warp, lane 0 issues ----
    const int warp = t >> 5;
    const int lane = t & 31;
    if (lane == 0) {
        asm volatile("fence.proxy.async.shared::cta;" ::: "memory");
        uint32_t saddr = smem_u32(s_col);
        // out[bc][h][wbase..]:  float offset = bc*H_C*W_C + h*W_C + wbase
        float* dst_base = out + (size_t)bc * (H_C * W_C) + wbase;
#pragma unroll
        for (int i = 0; i < 8; i++) {
            int h = warp * 8 + i;
            float* dst = dst_base + (size_t)h * W_C;
            asm volatile(
                "cp.async.bulk.global.shared::cta.bulk_group [%0], [%1], %2;"
                :: "l"(dst), "r"(saddr), "r"(CHUNK_BYTES) : "memory");
        }
        asm volatile("cp.async.bulk.commit_group;" ::: "memory");
        asm volatile("cp.async.bulk.wait_group 0;" ::: "memory");
    }
}

extern "C" void kernel_launch(void* const* d_in, const int* in_sizes, int n_in,
                              void* d_out, int out_size) {
    const float* bev = (const float*)d_in[0];
    float* out = (float*)d_out;

    bev2cyl_tma<<<BC_ * NCHUNK, 256>>>(bev, out);   // 2048 CTAs
}